// round 12
// baseline (speedup 1.0000x reference)
#include <cuda_runtime.h>

#define BB 2
#define DD 160
#define HH 192
#define WW 160
#define NVOX (BB*DD*HH*WW)   // 9,830,400
#define KS 729.0f

// Scratch: 5 fields (W-sums), field-major: gA[f][b][d][h][w]
__device__ float gA[5 * NVOX];
__device__ double g_acc;          // static 0; reset by last block each run
__device__ unsigned int g_done;   // static 0; reset by last block each run

// ---------------------------------------------------------------------------
// Pass 1 (R5 version, proven): along W, 3 rows/block, 480 threads, coalesced.
// ---------------------------------------------------------------------------
__global__ void k_pass1(const float* __restrict__ in, const float* __restrict__ tg) {
    __shared__ float sI[3][WW];
    __shared__ float sT[3][WW];
    const int w = threadIdx.x;
    const int r = threadIdx.y;
    const size_t base = ((size_t)blockIdx.x * 3 + r) * WW;
    float iv = in[base + w];
    float tv = (tg[base + w] + 1.0f) * 0.5f;
    sI[r][w] = iv;
    sT[r][w] = tv;
    __syncthreads();
    float a0 = 0.f, a1 = 0.f, a2 = 0.f, a3 = 0.f, a4 = 0.f;
#pragma unroll
    for (int j = -4; j <= 4; ++j) {
        int x = w + j;
        if (x >= 0 && x < WW) {
            float a = sI[r][x], b = sT[r][x];
            a0 += a;
            a1 += b;
            a2 += a * a;
            a3 += b * b;
            a4 += a * b;
        }
    }
    gA[0 * (size_t)NVOX + base + w] = a0;
    gA[1 * (size_t)NVOX + base + w] = a1;
    gA[2 * (size_t)NVOX + base + w] = a2;
    gA[3 * (size_t)NVOX + base + w] = a3;
    gA[4 * (size_t)NVOX + base + w] = a4;
}

// ---------------------------------------------------------------------------
// Fused pass 2+3: 512 threads = 16 w x 32 dd lanes (KD=1). Walk H with
// per-thread running sums. Lead plane prefetched to regs; trail loaded at
// use (L2 hit). D box-sum via 9 smem taps, stride-16 rows (conflict-free:
// warp = 2 dd-rows x 16 tx -> 32 distinct banks). Double-buffered smem,
// ONE sync per step. 560 blocks for barrier-latency overlap.
// ---------------------------------------------------------------------------
#define WT 16
#define NDD 32
#define DOUT 24
#define HCH 48
#define NT 512

__device__ __forceinline__ float cc_val(float r0, float r1, float r2, float r3, float r4) {
    const float inv = 1.0f / KS;
    float cross = r4 - r0 * r1 * inv;
    float T_var = r3 - r1 * r1 * inv;
    float I_var = r2 - r0 * r0 * inv;
    return cross * cross / (T_var * I_var + 1e-5f);
}

__global__ __launch_bounds__(NT) void k_pass23(float* __restrict__ out) {
    __shared__ float buf[2][5][NDD][WT];

    const int tid = threadIdx.x;
    const int tx = tid & (WT - 1);
    const int dd = tid >> 4;             // 0..31 (NT=512)
    const int w0 = blockIdx.x * WT;
    const int dtile = blockIdx.y * DOUT;
    const int hchunks = HH / HCH;        // 4
    const int b = blockIdx.z / hchunks;
    const int c0 = (blockIdx.z % hchunks) * HCH;

    const float* __restrict__ A = gA;

    const int d_in = dtile - 4 + dd;
    const bool din = (d_in >= 0 && d_in < DD);
    const size_t gb = din ? ((((size_t)b * DD + d_in) * HH) * WW + w0 + tx) : 0;

    float r0 = 0.f, r1 = 0.f, r2 = 0.f, r3 = 0.f, r4 = 0.f;
    // init running H-sum over planes [c0-5, c0+3]
    if (din) {
        for (int h = c0 - 5; h <= c0 + 3; ++h) {
            if (h >= 0) {
                size_t i = gb + (size_t)h * WW;
                r0 += A[i];
                r1 += A[i + (size_t)NVOX];
                r2 += A[i + 2 * (size_t)NVOX];
                r3 += A[i + 3 * (size_t)NVOX];
                r4 += A[i + 4 * (size_t)NVOX];
            }
        }
    }
    // preload lead plane (h = c0+4; always < HH for this chunking)
    float l0, l1, l2, l3, l4;
    {
        size_t il = gb + (size_t)(c0 + 4) * WW;
        l0 = din ? A[il] : 0.f;
        l1 = din ? A[il + (size_t)NVOX] : 0.f;
        l2 = din ? A[il + 2 * (size_t)NVOX] : 0.f;
        l3 = din ? A[il + 3 * (size_t)NVOX] : 0.f;
        l4 = din ? A[il + 4 * (size_t)NVOX] : 0.f;
    }

    const bool dout = (dd >= 4 && dd <= 27) && (dtile + dd - 4 < DD);
    float facc = 0.f;
    int p = 0;

    for (int c = c0; c < c0 + HCH; ++c) {
        // trail (h = c-5): L2 hit (this thread loaded it as lead 9 steps ago)
        {
            bool vt = din && (c - 5 >= 0);
            size_t it = gb + (size_t)(c - 5) * WW;
            float t0 = vt ? A[it] : 0.f;
            float t1 = vt ? A[it + (size_t)NVOX] : 0.f;
            float t2 = vt ? A[it + 2 * (size_t)NVOX] : 0.f;
            float t3 = vt ? A[it + 3 * (size_t)NVOX] : 0.f;
            float t4 = vt ? A[it + 4 * (size_t)NVOX] : 0.f;
            r0 += l0 - t0;
            r1 += l1 - t1;
            r2 += l2 - t2;
            r3 += l3 - t3;
            r4 += l4 - t4;
        }
        buf[p][0][dd][tx] = r0;
        buf[p][1][dd][tx] = r1;
        buf[p][2][dd][tx] = r2;
        buf[p][3][dd][tx] = r3;
        buf[p][4][dd][tx] = r4;

        // prefetch lead for step c+1 (h = c+5)
        {
            bool vl = din && (c + 5 < HH);
            size_t il = gb + (size_t)(c + 5) * WW;
            l0 = vl ? A[il] : 0.f;
            l1 = vl ? A[il + (size_t)NVOX] : 0.f;
            l2 = vl ? A[il + 2 * (size_t)NVOX] : 0.f;
            l3 = vl ? A[il + 3 * (size_t)NVOX] : 0.f;
            l4 = vl ? A[il + 4 * (size_t)NVOX] : 0.f;
        }

        __syncthreads();

        if (dout) {
            float s0 = 0.f, s1 = 0.f, s2 = 0.f, s3 = 0.f, s4 = 0.f;
#pragma unroll
            for (int j = 0; j < 9; ++j) {
                int q = dd - 4 + j;
                s0 += buf[p][0][q][tx];
                s1 += buf[p][1][q][tx];
                s2 += buf[p][2][q][tx];
                s3 += buf[p][3][q][tx];
                s4 += buf[p][4][q][tx];
            }
            facc += cc_val(s0, s1, s2, s3, s4);
        }
        p ^= 1;
    }

    // block reduction (promote to double)
    double acc = (double)facc;
#pragma unroll
    for (int off = 16; off; off >>= 1) acc += __shfl_down_sync(0xffffffffu, acc, off);
    __shared__ double sred[16];
    int lane = tid & 31;
    int wid = tid >> 5;
    if (lane == 0) sred[wid] = acc;
    __syncthreads();
    if (wid == 0) {
        double a = (lane < 16) ? sred[lane] : 0.0;
#pragma unroll
        for (int off = 8; off; off >>= 1) a += __shfl_down_sync(0xffffffffu, a, off);
        if (lane == 0) {
            atomicAdd(&g_acc, a);
            __threadfence();
            unsigned int total = gridDim.x * gridDim.y * gridDim.z;
            unsigned int old = atomicAdd(&g_done, 1u);
            if (old == total - 1) {
                out[0] = (float)(-g_acc / (double)NVOX);
                g_acc = 0.0;
                g_done = 0u;
            }
        }
    }
}

extern "C" void kernel_launch(void* const* d_in, const int* in_sizes, int n_in,
                              void* d_out, int out_size) {
    const float* in = (const float*)d_in[0];
    const float* tg = (const float*)d_in[1];
    float* out = (float*)d_out;

    {
        dim3 blk(WW, 3);
        k_pass1<<<(BB * DD * HH) / 3, blk>>>(in, tg);
    }
    {
        // 10 w-tiles x 7 d-tiles x (2 b x 4 h-chunks) = 560 blocks
        dim3 grid(WW / WT, (DD + DOUT - 1) / DOUT, BB * (HH / HCH));
        k_pass23<<<grid, NT>>>(out);
    }
}

// round 13
// speedup vs baseline: 1.5728x; 1.5728x over previous
#include <cuda_runtime.h>

#define BB 2
#define DD 160
#define HH 192
#define WW 160
#define NVOX (BB*DD*HH*WW)   // 9,830,400
#define KS 729.0f

// Scratch: 5 fields (W-sums), field-major: gA[f][b][d][h][w]
__device__ float gA[5 * NVOX];
__device__ double g_acc;          // static 0; reset by last block each run
__device__ unsigned int g_done;   // static 0; reset by last block each run

// ---------------------------------------------------------------------------
// Pass 1 (R5 version, proven): along W, 3 rows/block, 480 threads, coalesced.
// ---------------------------------------------------------------------------
__global__ void k_pass1(const float* __restrict__ in, const float* __restrict__ tg) {
    __shared__ float sI[3][WW];
    __shared__ float sT[3][WW];
    const int w = threadIdx.x;
    const int r = threadIdx.y;
    const size_t base = ((size_t)blockIdx.x * 3 + r) * WW;
    float iv = in[base + w];
    float tv = (tg[base + w] + 1.0f) * 0.5f;
    sI[r][w] = iv;
    sT[r][w] = tv;
    __syncthreads();
    float a0 = 0.f, a1 = 0.f, a2 = 0.f, a3 = 0.f, a4 = 0.f;
#pragma unroll
    for (int j = -4; j <= 4; ++j) {
        int x = w + j;
        if (x >= 0 && x < WW) {
            float a = sI[r][x], b = sT[r][x];
            a0 += a;
            a1 += b;
            a2 += a * a;
            a3 += b * b;
            a4 += a * b;
        }
    }
    gA[0 * (size_t)NVOX + base + w] = a0;
    gA[1 * (size_t)NVOX + base + w] = a1;
    gA[2 * (size_t)NVOX + base + w] = a2;
    gA[3 * (size_t)NVOX + base + w] = a3;
    gA[4 * (size_t)NVOX + base + w] = a4;
}

// ---------------------------------------------------------------------------
// Fused pass 2+3: 512 threads = 16 w x 32 dd lanes. Walk H with per-thread
// running sums; lead AND trail planes prefetched to registers (R5-proven).
// D box-sum via TWO-LEVEL smem taps: partial-3 sums then 3 partials per
// output (30 LDS vs 45). Single-buffered smem (2 barriers/step separate
// writers/readers). Last block folds in the final reduction.
// ---------------------------------------------------------------------------
#define WT 16
#define NDD 32
#define DOUT 24
#define HCH 96
#define NT 512

__device__ __forceinline__ float cc_val(float r0, float r1, float r2, float r3, float r4) {
    const float inv = 1.0f / KS;
    float cross = r4 - r0 * r1 * inv;
    float T_var = r3 - r1 * r1 * inv;
    float I_var = r2 - r0 * r0 * inv;
    return cross * cross / (T_var * I_var + 1e-5f);
}

__global__ __launch_bounds__(NT) void k_pass23(float* __restrict__ out) {
    __shared__ float raw[5][NDD][WT];    // H-sum rows, this step
    __shared__ float part[5][NDD][WT];   // partial-3 sums over dd

    const int tid = threadIdx.x;
    const int tx = tid & (WT - 1);
    const int dd = tid >> 4;             // 0..31
    const int w0 = blockIdx.x * WT;
    const int dtile = blockIdx.y * DOUT;
    const int hchunks = HH / HCH;        // 2
    const int b = blockIdx.z / hchunks;
    const int c0 = (blockIdx.z % hchunks) * HCH;

    const float* __restrict__ A = gA;

    const int d_in = dtile - 4 + dd;
    const bool din = (d_in >= 0 && d_in < DD);
    const size_t gb = din ? ((((size_t)b * DD + d_in) * HH) * WW + w0 + tx) : 0;

    float r0 = 0.f, r1 = 0.f, r2 = 0.f, r3 = 0.f, r4 = 0.f;
    // init running H-sum over planes [c0-5, c0+3]
    if (din) {
        for (int h = c0 - 5; h <= c0 + 3; ++h) {
            if (h >= 0) {
                size_t i = gb + (size_t)h * WW;
                r0 += A[i];
                r1 += A[i + (size_t)NVOX];
                r2 += A[i + 2 * (size_t)NVOX];
                r3 += A[i + 3 * (size_t)NVOX];
                r4 += A[i + 4 * (size_t)NVOX];
            }
        }
    }
    // preload lead (h=c0+4, always valid) and trail (h=c0-5)
    float l0, l1, l2, l3, l4, t0, t1, t2, t3, t4;
    {
        size_t il = gb + (size_t)(c0 + 4) * WW;
        l0 = din ? A[il] : 0.f;
        l1 = din ? A[il + (size_t)NVOX] : 0.f;
        l2 = din ? A[il + 2 * (size_t)NVOX] : 0.f;
        l3 = din ? A[il + 3 * (size_t)NVOX] : 0.f;
        l4 = din ? A[il + 4 * (size_t)NVOX] : 0.f;
        bool vt = din && (c0 - 5 >= 0);
        size_t it = gb + (size_t)(c0 - 5) * WW;
        t0 = vt ? A[it] : 0.f;
        t1 = vt ? A[it + (size_t)NVOX] : 0.f;
        t2 = vt ? A[it + 2 * (size_t)NVOX] : 0.f;
        t3 = vt ? A[it + 3 * (size_t)NVOX] : 0.f;
        t4 = vt ? A[it + 4 * (size_t)NVOX] : 0.f;
    }

    const bool build = (dd <= 29);
    const bool dout = (dd >= 4 && dd <= 27) && (dtile + dd - 4 < DD);
    float facc = 0.f;

    for (int c = c0; c < c0 + HCH; ++c) {
        // advance running H-sum to window [c-4, c+4] (pure FMA, no loads)
        r0 += l0 - t0;
        r1 += l1 - t1;
        r2 += l2 - t2;
        r3 += l3 - t3;
        r4 += l4 - t4;
        raw[0][dd][tx] = r0;
        raw[1][dd][tx] = r1;
        raw[2][dd][tx] = r2;
        raw[3][dd][tx] = r3;
        raw[4][dd][tx] = r4;

        // prefetch for step c+1: lead h=c+5, trail h=c-4
        {
            bool vl = din && (c + 5 < HH);
            size_t il = gb + (size_t)(c + 5) * WW;
            l0 = vl ? A[il] : 0.f;
            l1 = vl ? A[il + (size_t)NVOX] : 0.f;
            l2 = vl ? A[il + 2 * (size_t)NVOX] : 0.f;
            l3 = vl ? A[il + 3 * (size_t)NVOX] : 0.f;
            l4 = vl ? A[il + 4 * (size_t)NVOX] : 0.f;
            bool vt = din && (c - 4 >= 0);
            size_t it = gb + (size_t)(c - 4) * WW;
            t0 = vt ? A[it] : 0.f;
            t1 = vt ? A[it + (size_t)NVOX] : 0.f;
            t2 = vt ? A[it + 2 * (size_t)NVOX] : 0.f;
            t3 = vt ? A[it + 3 * (size_t)NVOX] : 0.f;
            t4 = vt ? A[it + 4 * (size_t)NVOX] : 0.f;
        }

        __syncthreads();

        // level 1: partial-3 sums over dd
        if (build) {
            part[0][dd][tx] = raw[0][dd][tx] + raw[0][dd + 1][tx] + raw[0][dd + 2][tx];
            part[1][dd][tx] = raw[1][dd][tx] + raw[1][dd + 1][tx] + raw[1][dd + 2][tx];
            part[2][dd][tx] = raw[2][dd][tx] + raw[2][dd + 1][tx] + raw[2][dd + 2][tx];
            part[3][dd][tx] = raw[3][dd][tx] + raw[3][dd + 1][tx] + raw[3][dd + 2][tx];
            part[4][dd][tx] = raw[4][dd][tx] + raw[4][dd + 1][tx] + raw[4][dd + 2][tx];
        }

        __syncthreads();

        // level 2: 9-window = partials at dd-4, dd-1, dd+2
        if (dout) {
            float s0 = part[0][dd - 4][tx] + part[0][dd - 1][tx] + part[0][dd + 2][tx];
            float s1 = part[1][dd - 4][tx] + part[1][dd - 1][tx] + part[1][dd + 2][tx];
            float s2 = part[2][dd - 4][tx] + part[2][dd - 1][tx] + part[2][dd + 2][tx];
            float s3 = part[3][dd - 4][tx] + part[3][dd - 1][tx] + part[3][dd + 2][tx];
            float s4 = part[4][dd - 4][tx] + part[4][dd - 1][tx] + part[4][dd + 2][tx];
            facc += cc_val(s0, s1, s2, s3, s4);
        }
    }

    // block reduction (promote to double)
    double acc = (double)facc;
#pragma unroll
    for (int off = 16; off; off >>= 1) acc += __shfl_down_sync(0xffffffffu, acc, off);
    __shared__ double sred[16];
    int lane = tid & 31;
    int wid = tid >> 5;
    if (lane == 0) sred[wid] = acc;
    __syncthreads();
    if (wid == 0) {
        double a = (lane < 16) ? sred[lane] : 0.0;
#pragma unroll
        for (int off = 8; off; off >>= 1) a += __shfl_down_sync(0xffffffffu, a, off);
        if (lane == 0) {
            atomicAdd(&g_acc, a);
            __threadfence();
            unsigned int total = gridDim.x * gridDim.y * gridDim.z;
            unsigned int old = atomicAdd(&g_done, 1u);
            if (old == total - 1) {
                out[0] = (float)(-g_acc / (double)NVOX);
                g_acc = 0.0;
                g_done = 0u;
            }
        }
    }
}

extern "C" void kernel_launch(void* const* d_in, const int* in_sizes, int n_in,
                              void* d_out, int out_size) {
    const float* in = (const float*)d_in[0];
    const float* tg = (const float*)d_in[1];
    float* out = (float*)d_out;

    {
        dim3 blk(WW, 3);
        k_pass1<<<(BB * DD * HH) / 3, blk>>>(in, tg);
    }
    {
        // 10 w-tiles x 7 d-tiles x (2 b x 2 h-chunks) = 280 blocks
        dim3 grid(WW / WT, (DD + DOUT - 1) / DOUT, BB * (HH / HCH));
        k_pass23<<<grid, NT>>>(out);
    }
}

// round 14
// speedup vs baseline: 1.5827x; 1.0063x over previous
#include <cuda_runtime.h>

#define BB 2
#define DD 160
#define HH 192
#define WW 160
#define NVOX (BB*DD*HH*WW)   // 9,830,400
#define KS 729.0f

// Scratch: 5 fields (W-sums), field-major: gA[f][b][d][h][w]
__device__ float gA[5 * NVOX];
__device__ double g_acc;          // static 0; reset by last block each run
__device__ unsigned int g_done;   // static 0; reset by last block each run

// ---------------------------------------------------------------------------
// Pass 1 (R5 version, proven): along W, 3 rows/block, 480 threads, coalesced.
// ---------------------------------------------------------------------------
__global__ void k_pass1(const float* __restrict__ in, const float* __restrict__ tg) {
    __shared__ float sI[3][WW];
    __shared__ float sT[3][WW];
    const int w = threadIdx.x;
    const int r = threadIdx.y;
    const size_t base = ((size_t)blockIdx.x * 3 + r) * WW;
    float iv = in[base + w];
    float tv = (tg[base + w] + 1.0f) * 0.5f;
    sI[r][w] = iv;
    sT[r][w] = tv;
    __syncthreads();
    float a0 = 0.f, a1 = 0.f, a2 = 0.f, a3 = 0.f, a4 = 0.f;
#pragma unroll
    for (int j = -4; j <= 4; ++j) {
        int x = w + j;
        if (x >= 0 && x < WW) {
            float a = sI[r][x], b = sT[r][x];
            a0 += a;
            a1 += b;
            a2 += a * a;
            a3 += b * b;
            a4 += a * b;
        }
    }
    gA[0 * (size_t)NVOX + base + w] = a0;
    gA[1 * (size_t)NVOX + base + w] = a1;
    gA[2 * (size_t)NVOX + base + w] = a2;
    gA[3 * (size_t)NVOX + base + w] = a3;
    gA[4 * (size_t)NVOX + base + w] = a4;
}

// ---------------------------------------------------------------------------
// Fused pass 2+3: 512 threads = 16 w x 32 dd lanes. Walk H with per-thread
// running sums; lead AND trail planes prefetched to registers. Two-level
// D box-sum in smem (partial-3 then 3 partials). HCH=48 -> 560 blocks,
// __launch_bounds__(512,3) -> 3 resident blocks/SM to hide the 2 barriers.
// ---------------------------------------------------------------------------
#define WT 16
#define NDD 32
#define DOUT 24
#define HCH 48
#define NT 512

__device__ __forceinline__ float cc_val(float r0, float r1, float r2, float r3, float r4) {
    const float inv = 1.0f / KS;
    float cross = r4 - r0 * r1 * inv;
    float T_var = r3 - r1 * r1 * inv;
    float I_var = r2 - r0 * r0 * inv;
    return cross * cross / (T_var * I_var + 1e-5f);
}

__global__ __launch_bounds__(NT, 3) void k_pass23(float* __restrict__ out) {
    __shared__ float raw[5][NDD][WT];    // H-sum rows, this step
    __shared__ float part[5][NDD][WT];   // partial-3 sums over dd

    const int tid = threadIdx.x;
    const int tx = tid & (WT - 1);
    const int dd = tid >> 4;             // 0..31
    const int w0 = blockIdx.x * WT;
    const int dtile = blockIdx.y * DOUT;
    const int hchunks = HH / HCH;        // 4
    const int b = blockIdx.z / hchunks;
    const int c0 = (blockIdx.z % hchunks) * HCH;

    const float* __restrict__ A = gA;

    const int d_in = dtile - 4 + dd;
    const bool din = (d_in >= 0 && d_in < DD);
    const size_t gb = din ? ((((size_t)b * DD + d_in) * HH) * WW + w0 + tx) : 0;

    float r0 = 0.f, r1 = 0.f, r2 = 0.f, r3 = 0.f, r4 = 0.f;
    // init running H-sum over planes [c0-5, c0+3]
    if (din) {
        for (int h = c0 - 5; h <= c0 + 3; ++h) {
            if (h >= 0) {
                size_t i = gb + (size_t)h * WW;
                r0 += A[i];
                r1 += A[i + (size_t)NVOX];
                r2 += A[i + 2 * (size_t)NVOX];
                r3 += A[i + 3 * (size_t)NVOX];
                r4 += A[i + 4 * (size_t)NVOX];
            }
        }
    }
    // preload lead (h=c0+4, always valid) and trail (h=c0-5)
    float l0, l1, l2, l3, l4, t0, t1, t2, t3, t4;
    {
        size_t il = gb + (size_t)(c0 + 4) * WW;
        l0 = din ? A[il] : 0.f;
        l1 = din ? A[il + (size_t)NVOX] : 0.f;
        l2 = din ? A[il + 2 * (size_t)NVOX] : 0.f;
        l3 = din ? A[il + 3 * (size_t)NVOX] : 0.f;
        l4 = din ? A[il + 4 * (size_t)NVOX] : 0.f;
        bool vt = din && (c0 - 5 >= 0);
        size_t it = gb + (size_t)(c0 - 5) * WW;
        t0 = vt ? A[it] : 0.f;
        t1 = vt ? A[it + (size_t)NVOX] : 0.f;
        t2 = vt ? A[it + 2 * (size_t)NVOX] : 0.f;
        t3 = vt ? A[it + 3 * (size_t)NVOX] : 0.f;
        t4 = vt ? A[it + 4 * (size_t)NVOX] : 0.f;
    }

    const bool build = (dd <= 29);
    const bool dout = (dd >= 4 && dd <= 27) && (dtile + dd - 4 < DD);
    float facc = 0.f;

    for (int c = c0; c < c0 + HCH; ++c) {
        // advance running H-sum to window [c-4, c+4] (pure FMA, no loads)
        r0 += l0 - t0;
        r1 += l1 - t1;
        r2 += l2 - t2;
        r3 += l3 - t3;
        r4 += l4 - t4;
        raw[0][dd][tx] = r0;
        raw[1][dd][tx] = r1;
        raw[2][dd][tx] = r2;
        raw[3][dd][tx] = r3;
        raw[4][dd][tx] = r4;

        // prefetch for step c+1: lead h=c+5, trail h=c-4
        {
            bool vl = din && (c + 5 < HH);
            size_t il = gb + (size_t)(c + 5) * WW;
            l0 = vl ? A[il] : 0.f;
            l1 = vl ? A[il + (size_t)NVOX] : 0.f;
            l2 = vl ? A[il + 2 * (size_t)NVOX] : 0.f;
            l3 = vl ? A[il + 3 * (size_t)NVOX] : 0.f;
            l4 = vl ? A[il + 4 * (size_t)NVOX] : 0.f;
            bool vt = din && (c - 4 >= 0);
            size_t it = gb + (size_t)(c - 4) * WW;
            t0 = vt ? A[it] : 0.f;
            t1 = vt ? A[it + (size_t)NVOX] : 0.f;
            t2 = vt ? A[it + 2 * (size_t)NVOX] : 0.f;
            t3 = vt ? A[it + 3 * (size_t)NVOX] : 0.f;
            t4 = vt ? A[it + 4 * (size_t)NVOX] : 0.f;
        }

        __syncthreads();

        // level 1: partial-3 sums over dd
        if (build) {
            part[0][dd][tx] = raw[0][dd][tx] + raw[0][dd + 1][tx] + raw[0][dd + 2][tx];
            part[1][dd][tx] = raw[1][dd][tx] + raw[1][dd + 1][tx] + raw[1][dd + 2][tx];
            part[2][dd][tx] = raw[2][dd][tx] + raw[2][dd + 1][tx] + raw[2][dd + 2][tx];
            part[3][dd][tx] = raw[3][dd][tx] + raw[3][dd + 1][tx] + raw[3][dd + 2][tx];
            part[4][dd][tx] = raw[4][dd][tx] + raw[4][dd + 1][tx] + raw[4][dd + 2][tx];
        }

        __syncthreads();

        // level 2: 9-window = partials at dd-4, dd-1, dd+2
        if (dout) {
            float s0 = part[0][dd - 4][tx] + part[0][dd - 1][tx] + part[0][dd + 2][tx];
            float s1 = part[1][dd - 4][tx] + part[1][dd - 1][tx] + part[1][dd + 2][tx];
            float s2 = part[2][dd - 4][tx] + part[2][dd - 1][tx] + part[2][dd + 2][tx];
            float s3 = part[3][dd - 4][tx] + part[3][dd - 1][tx] + part[3][dd + 2][tx];
            float s4 = part[4][dd - 4][tx] + part[4][dd - 1][tx] + part[4][dd + 2][tx];
            facc += cc_val(s0, s1, s2, s3, s4);
        }
    }

    // block reduction (promote to double)
    double acc = (double)facc;
#pragma unroll
    for (int off = 16; off; off >>= 1) acc += __shfl_down_sync(0xffffffffu, acc, off);
    __shared__ double sred[16];
    int lane = tid & 31;
    int wid = tid >> 5;
    if (lane == 0) sred[wid] = acc;
    __syncthreads();
    if (wid == 0) {
        double a = (lane < 16) ? sred[lane] : 0.0;
#pragma unroll
        for (int off = 8; off; off >>= 1) a += __shfl_down_sync(0xffffffffu, a, off);
        if (lane == 0) {
            atomicAdd(&g_acc, a);
            __threadfence();
            unsigned int total = gridDim.x * gridDim.y * gridDim.z;
            unsigned int old = atomicAdd(&g_done, 1u);
            if (old == total - 1) {
                out[0] = (float)(-g_acc / (double)NVOX);
                g_acc = 0.0;
                g_done = 0u;
            }
        }
    }
}

extern "C" void kernel_launch(void* const* d_in, const int* in_sizes, int n_in,
                              void* d_out, int out_size) {
    const float* in = (const float*)d_in[0];
    const float* tg = (const float*)d_in[1];
    float* out = (float*)d_out;

    {
        dim3 blk(WW, 3);
        k_pass1<<<(BB * DD * HH) / 3, blk>>>(in, tg);
    }
    {
        // 10 w-tiles x 7 d-tiles x (2 b x 4 h-chunks) = 560 blocks
        dim3 grid(WW / WT, (DD + DOUT - 1) / DOUT, BB * (HH / HCH));
        k_pass23<<<grid, NT>>>(out);
    }
}

// round 15
// speedup vs baseline: 1.7803x; 1.1248x over previous
#include <cuda_runtime.h>

#define BB 2
#define DD 160
#define HH 192
#define WW 160
#define NVOX (BB*DD*HH*WW)   // 9,830,400
#define KS 729.0f

// Scratch: 5 fields (H-box-sums of products), field-major: gA[f][b][d][h][w]
__device__ float gA[5 * NVOX];
__device__ double g_acc;          // static 0; reset by last block each run
__device__ unsigned int g_done;   // static 0; reset by last block each run

// ---------------------------------------------------------------------------
// Pass 1: H-direction box sum of the 5 product fields. Thread per (b,d,w,
// h-chunk), running sum along h. Coalesced (w fastest), NO smem, NO barriers.
// Products recomputed at lead/trail from raw inputs (trail = L2 hit).
// ---------------------------------------------------------------------------
#define H1 48
#define NTH1 (BB*DD*WW*(HH/H1))   // 204800

__global__ __launch_bounds__(256) void k_pass1(const float* __restrict__ in,
                                               const float* __restrict__ tg) {
    int tid = blockIdx.x * 256 + threadIdx.x;
    int w = tid % WW;
    int rest = tid / WW;
    int d = rest % DD;
    int rest2 = rest / DD;
    int b = rest2 % BB;
    int chunk = rest2 / BB;            // 0..3
    const int c0 = chunk * H1;

    const size_t gb = (((size_t)b * DD + d) * HH) * WW + w;   // h stride WW

    float r0 = 0.f, r1 = 0.f, r2 = 0.f, r3 = 0.f, r4 = 0.f;
    // init over h in [c0-5, c0+3]
    for (int h = c0 - 5; h <= c0 + 3; ++h) {
        if (h >= 0) {
            float iv = in[gb + (size_t)h * WW];
            float tv = (tg[gb + (size_t)h * WW] + 1.0f) * 0.5f;
            r0 += iv; r1 += tv; r2 += iv * iv; r3 += tv * tv; r4 += iv * tv;
        }
    }

    // preload lead (h=c0+4, always <HH) and trail (h=c0-5)
    float li = in[gb + (size_t)(c0 + 4) * WW];
    float lt = (tg[gb + (size_t)(c0 + 4) * WW] + 1.0f) * 0.5f;
    float ti = 0.f, tt = 0.f;
    if (c0 - 5 >= 0) {
        ti = in[gb + (size_t)(c0 - 5) * WW];
        tt = (tg[gb + (size_t)(c0 - 5) * WW] + 1.0f) * 0.5f;
    }

    for (int c = c0; c < c0 + H1; ++c) {
        r0 += li - ti;
        r1 += lt - tt;
        r2 += li * li - ti * ti;
        r3 += lt * lt - tt * tt;
        r4 += li * lt - ti * tt;

        // prefetch next lead (h=c+5) / trail (h=c-4)
        bool vl = (c + 5 < HH);
        bool vt = (c - 4 >= 0);
        size_t il = gb + (size_t)(c + 5) * WW;
        size_t it = gb + (size_t)(c - 4) * WW;
        float nli = vl ? in[il] : 0.f;
        float nlt = vl ? (tg[il] + 1.0f) * 0.5f : 0.f;
        float nti = vt ? in[it] : 0.f;
        float ntt = vt ? (tg[it] + 1.0f) * 0.5f : 0.f;

        size_t o = gb + (size_t)c * WW;
        gA[0 * (size_t)NVOX + o] = r0;
        gA[1 * (size_t)NVOX + o] = r1;
        gA[2 * (size_t)NVOX + o] = r2;
        gA[3 * (size_t)NVOX + o] = r3;
        gA[4 * (size_t)NVOX + o] = r4;

        li = nli; lt = nlt; ti = nti; tt = ntt;
    }
}

// ---------------------------------------------------------------------------
// Pass 2+3 (smem-free): warp lanes = 32 consecutive w (24 outputs, shuffle
// halo). Each thread walks D with register running sums (lead prefetch,
// trail prefetch). 9-tap W box via two-level warp shuffles. No barriers in
// the main loop. Last block writes the final result.
// ---------------------------------------------------------------------------
#define NWT 7              // w tiles of 24 outputs (covers 160 with padding)
#define DC 80              // d chunk
#define NT2 256
#define WARPS_PER_BLK (NT2/32)
#define TOTWARPS (BB*HH*NWT*(DD/DC))   // 2*192*7*2 = 5376

__device__ __forceinline__ float cc_val(float r0, float r1, float r2, float r3, float r4) {
    const float inv = 1.0f / KS;
    float cross = r4 - r0 * r1 * inv;
    float T_var = r3 - r1 * r1 * inv;
    float I_var = r2 - r0 * r0 * inv;
    return cross * cross / (T_var * I_var + 1e-5f);
}

__device__ __forceinline__ float box9_shfl(float r) {
    // s3[i] = r[i] + r[i+1] + r[i+2]
    float s3 = r + __shfl_down_sync(0xffffffffu, r, 1)
                 + __shfl_down_sync(0xffffffffu, r, 2);
    // out[i] = s3[i-4] + s3[i-1] + s3[i+2]  (valid for lanes 4..27)
    return __shfl_up_sync(0xffffffffu, s3, 4)
         + __shfl_up_sync(0xffffffffu, s3, 1)
         + __shfl_down_sync(0xffffffffu, s3, 2);
}

__global__ __launch_bounds__(NT2) void k_pass23(float* __restrict__ out) {
    const int lane = threadIdx.x & 31;
    const int wgid = blockIdx.x * WARPS_PER_BLK + (threadIdx.x >> 5);

    int wt = wgid % NWT;
    int rest = wgid / NWT;
    int h = rest % HH;
    int rest2 = rest / HH;
    int b = rest2 % BB;
    int dchunk = rest2 / BB;           // 0..1
    const int d0 = dchunk * DC;

    const int w = wt * 24 - 4 + lane;  // -4 .. 170
    const bool win = (w >= 0 && w < WW);
    const float* __restrict__ A = gA;

    // base at d=0 for (b, h, w); d stride = HH*WW
    const size_t gb = win ? (((size_t)b * DD * HH + h) * WW + w) : 0;
    const size_t ds = (size_t)HH * WW;

    float r0 = 0.f, r1 = 0.f, r2 = 0.f, r3 = 0.f, r4 = 0.f;
    if (win) {
        for (int dp = d0 - 5; dp <= d0 + 3; ++dp) {
            if (dp >= 0) {
                size_t i = gb + (size_t)dp * ds;
                r0 += A[i];
                r1 += A[i + (size_t)NVOX];
                r2 += A[i + 2 * (size_t)NVOX];
                r3 += A[i + 3 * (size_t)NVOX];
                r4 += A[i + 4 * (size_t)NVOX];
            }
        }
    }
    // preload lead (d0+4, always <DD) and trail (d0-5)
    float l0 = 0.f, l1 = 0.f, l2 = 0.f, l3 = 0.f, l4 = 0.f;
    float t0 = 0.f, t1 = 0.f, t2 = 0.f, t3 = 0.f, t4 = 0.f;
    if (win) {
        size_t il = gb + (size_t)(d0 + 4) * ds;
        l0 = A[il];
        l1 = A[il + (size_t)NVOX];
        l2 = A[il + 2 * (size_t)NVOX];
        l3 = A[il + 3 * (size_t)NVOX];
        l4 = A[il + 4 * (size_t)NVOX];
        if (d0 - 5 >= 0) {
            size_t it = gb + (size_t)(d0 - 5) * ds;
            t0 = A[it];
            t1 = A[it + (size_t)NVOX];
            t2 = A[it + 2 * (size_t)NVOX];
            t3 = A[it + 3 * (size_t)NVOX];
            t4 = A[it + 4 * (size_t)NVOX];
        }
    }

    const bool lout = (lane >= 4 && lane <= 27) && (w < WW);  // w>=0 implied
    float facc = 0.f;

    for (int c = d0; c < d0 + DC; ++c) {
        r0 += l0 - t0;
        r1 += l1 - t1;
        r2 += l2 - t2;
        r3 += l3 - t3;
        r4 += l4 - t4;

        // prefetch next lead (d=c+5) / trail (d=c-4)
        {
            bool vl = win && (c + 5 < DD);
            bool vt = win && (c - 4 >= 0);
            size_t il = gb + (size_t)(c + 5) * ds;
            size_t it = gb + (size_t)(c - 4) * ds;
            l0 = vl ? A[il] : 0.f;
            l1 = vl ? A[il + (size_t)NVOX] : 0.f;
            l2 = vl ? A[il + 2 * (size_t)NVOX] : 0.f;
            l3 = vl ? A[il + 3 * (size_t)NVOX] : 0.f;
            l4 = vl ? A[il + 4 * (size_t)NVOX] : 0.f;
            t0 = vt ? A[it] : 0.f;
            t1 = vt ? A[it + (size_t)NVOX] : 0.f;
            t2 = vt ? A[it + 2 * (size_t)NVOX] : 0.f;
            t3 = vt ? A[it + 3 * (size_t)NVOX] : 0.f;
            t4 = vt ? A[it + 4 * (size_t)NVOX] : 0.f;
        }

        // 9-tap W box sums via warp shuffles (no smem, no barriers)
        float s0 = box9_shfl(r0);
        float s1 = box9_shfl(r1);
        float s2 = box9_shfl(r2);
        float s3 = box9_shfl(r3);
        float s4 = box9_shfl(r4);

        if (lout) facc += cc_val(s0, s1, s2, s3, s4);
    }

    // block reduction (promote to double)
    double acc = (double)facc;
#pragma unroll
    for (int off = 16; off; off >>= 1) acc += __shfl_down_sync(0xffffffffu, acc, off);
    __shared__ double sred[WARPS_PER_BLK];
    int ln = threadIdx.x & 31;
    int wd = threadIdx.x >> 5;
    if (ln == 0) sred[wd] = acc;
    __syncthreads();
    if (wd == 0) {
        double a = (ln < WARPS_PER_BLK) ? sred[ln] : 0.0;
#pragma unroll
        for (int off = 4; off; off >>= 1) a += __shfl_down_sync(0xffffffffu, a, off);
        if (ln == 0) {
            atomicAdd(&g_acc, a);
            __threadfence();
            unsigned int old = atomicAdd(&g_done, 1u);
            if (old == (unsigned int)(TOTWARPS / WARPS_PER_BLK) - 1u) {
                out[0] = (float)(-g_acc / (double)NVOX);
                g_acc = 0.0;
                g_done = 0u;
            }
        }
    }
}

extern "C" void kernel_launch(void* const* d_in, const int* in_sizes, int n_in,
                              void* d_out, int out_size) {
    const float* in = (const float*)d_in[0];
    const float* tg = (const float*)d_in[1];
    float* out = (float*)d_out;

    k_pass1<<<NTH1 / 256, 256>>>(in, tg);
    k_pass23<<<TOTWARPS / WARPS_PER_BLK, NT2>>>(out);   // 672 blocks x 256
}

// round 17
// speedup vs baseline: 1.8793x; 1.0556x over previous
#include <cuda_runtime.h>

#define BB 2
#define DD 160
#define HH 192
#define WW 160
#define NVOX (BB*DD*HH*WW)     // 9,830,400 (real voxels, for the mean)
#define KS 729.0f

// Padded scratch: d -> [0,170) (real d = pad-5), w -> [0,176) (real w = pad-4).
// Halo regions are never written: __device__ zero-init keeps them 0 forever.
#define DDP 170
#define WWP 176
#define NVOXP (BB*DDP*HH*WWP)  // 11,489,280
#define NVOXP2 (NVOXP/2)       // float2 units
#define DSP2 (HH*WWP/2)        // d stride in float2 = 16896
#define HS2 (WWP/2)            // h stride in float2 = 88

__device__ float gA[5 * NVOXP];
__device__ double g_acc;          // static 0; reset by last block each run
__device__ unsigned int g_done;   // static 0; reset by last block each run

// ---------------------------------------------------------------------------
// Pass 1: products + H-direction running box sum, float2 across w.
// Thread per (b,d,w2,h-chunk). Coalesced, no smem, no barriers.
// ---------------------------------------------------------------------------
#define H1 32
#define W2 (WW/2)                       // 80
#define NTH1 (BB*DD*W2*(HH/H1))        // 2*160*80*6 = 153600

__global__ __launch_bounds__(256) void k_pass1(const float* __restrict__ in,
                                               const float* __restrict__ tg) {
    int tid = blockIdx.x * 256 + threadIdx.x;
    int w2 = tid % W2;
    int rest = tid / W2;
    int d = rest % DD;
    int rest2 = rest / DD;
    int b = rest2 % BB;
    int chunk = rest2 / BB;             // 0..5
    const int c0 = chunk * H1;

    const float2* __restrict__ IN = (const float2*)in;
    const float2* __restrict__ TG = (const float2*)tg;
    float2* __restrict__ GA = (float2*)gA;

    // input float2 base (h stride WW/2 = 80)
    const size_t ib = ((size_t)(b * DD + d) * HH) * W2 + w2;
    // output float2 base in padded layout (h stride 88), wp = 4+2*w2 -> /2 = 2+w2
    const size_t ob = ((size_t)(b * DDP + d + 5) * HH) * HS2 + 2 + w2;

    float2 r0 = {0, 0}, r1 = {0, 0}, r2 = {0, 0}, r3 = {0, 0}, r4 = {0, 0};
    for (int h = c0 - 5; h <= c0 + 3; ++h) {
        if (h >= 0) {
            float2 iv = IN[ib + (size_t)h * W2];
            float2 tv = TG[ib + (size_t)h * W2];
            tv.x = (tv.x + 1.0f) * 0.5f;
            tv.y = (tv.y + 1.0f) * 0.5f;
            r0.x += iv.x; r0.y += iv.y;
            r1.x += tv.x; r1.y += tv.y;
            r2.x += iv.x * iv.x; r2.y += iv.y * iv.y;
            r3.x += tv.x * tv.x; r3.y += tv.y * tv.y;
            r4.x += iv.x * tv.x; r4.y += iv.y * tv.y;
        }
    }

    float2 li = IN[ib + (size_t)(c0 + 4) * W2];
    float2 lt = TG[ib + (size_t)(c0 + 4) * W2];
    lt.x = (lt.x + 1.0f) * 0.5f; lt.y = (lt.y + 1.0f) * 0.5f;
    float2 ti = {0, 0}, tt = {0, 0};
    if (c0 - 5 >= 0) {
        ti = IN[ib + (size_t)(c0 - 5) * W2];
        tt = TG[ib + (size_t)(c0 - 5) * W2];
        tt.x = (tt.x + 1.0f) * 0.5f; tt.y = (tt.y + 1.0f) * 0.5f;
    }

    for (int c = c0; c < c0 + H1; ++c) {
        r0.x += li.x - ti.x;           r0.y += li.y - ti.y;
        r1.x += lt.x - tt.x;           r1.y += lt.y - tt.y;
        r2.x += li.x * li.x - ti.x * ti.x;  r2.y += li.y * li.y - ti.y * ti.y;
        r3.x += lt.x * lt.x - tt.x * tt.x;  r3.y += lt.y * lt.y - tt.y * tt.y;
        r4.x += li.x * lt.x - ti.x * tt.x;  r4.y += li.y * lt.y - ti.y * tt.y;

        // prefetch next lead (h=c+5) / trail (h=c-4)
        bool vl = (c + 5 < HH);
        bool vt = (c - 4 >= 0);
        float2 nli = {0, 0}, nlt = {0, 0}, nti = {0, 0}, ntt = {0, 0};
        if (vl) {
            nli = IN[ib + (size_t)(c + 5) * W2];
            nlt = TG[ib + (size_t)(c + 5) * W2];
            nlt.x = (nlt.x + 1.0f) * 0.5f; nlt.y = (nlt.y + 1.0f) * 0.5f;
        }
        if (vt) {
            nti = IN[ib + (size_t)(c - 4) * W2];
            ntt = TG[ib + (size_t)(c - 4) * W2];
            ntt.x = (ntt.x + 1.0f) * 0.5f; ntt.y = (ntt.y + 1.0f) * 0.5f;
        }

        size_t o = ob + (size_t)c * HS2;
        GA[0 * (size_t)NVOXP2 + o] = r0;
        GA[1 * (size_t)NVOXP2 + o] = r1;
        GA[2 * (size_t)NVOXP2 + o] = r2;
        GA[3 * (size_t)NVOXP2 + o] = r3;
        GA[4 * (size_t)NVOXP2 + o] = r4;

        li = nli; lt = nlt; ti = nti; tt = ntt;
    }
}

// ---------------------------------------------------------------------------
// Pass 2+3: warp lane owns 2 adjacent w (float2). D running sums in regs
// (lead+trail prefetch, all loads UNCONDITIONAL thanks to padding). 9-tap W
// box via pair-sum shuffles (6 SHFL + 7 ADD per field for 2 outputs).
// No smem, no barriers in the loop.
// ---------------------------------------------------------------------------
#define NWT 3              // w tiles of 56 outputs
#define DC 40              // d chunk
#define NT2 128
#define WPB (NT2/32)       // 4 warps per block
#define TOTWARPS (BB*HH*NWT*(DD/DC))   // 2*192*3*4 = 4608
#define NBLK2 (TOTWARPS/WPB)           // 1152

__device__ __forceinline__ float cc_val(float r0, float r1, float r2, float r3, float r4) {
    const float inv = 1.0f / KS;
    float cross = r4 - r0 * r1 * inv;
    float T_var = r3 - r1 * r1 * inv;
    float I_var = r2 - r0 * r0 * inv;
    return cross * cross / (T_var * I_var + 1e-5f);
}

__global__ __launch_bounds__(NT2) void k_pass23(float* __restrict__ out) {
    const int lane = threadIdx.x & 31;
    const int wgid = blockIdx.x * WPB + (threadIdx.x >> 5);

    int wt = wgid % NWT;
    int rest = wgid / NWT;
    int h = rest % HH;
    int rest2 = rest / HH;
    int b = rest2 % BB;
    int dchunk = rest2 / BB;           // 0..3
    const int d0 = dchunk * DC;

    const int w = wt * 56 - 4 + 2 * lane;      // element .x's w
    // padded float2 base at padded-d = d0 (= real d0-5), (w+4)/2
    const float2* __restrict__ G = (const float2*)gA;
    size_t base = ((size_t)(b * DDP + d0) * HH + h) * HS2 + (size_t)((w + 4) >> 1);

    const float2* p0 = G + 0 * (size_t)NVOXP2 + base;
    const float2* p1 = G + 1 * (size_t)NVOXP2 + base;
    const float2* p2 = G + 2 * (size_t)NVOXP2 + base;
    const float2* p3 = G + 3 * (size_t)NVOXP2 + base;
    const float2* p4 = G + 4 * (size_t)NVOXP2 + base;

    float2 r0 = {0,0}, r1 = {0,0}, r2 = {0,0}, r3 = {0,0}, r4 = {0,0};
#pragma unroll
    for (int k = 0; k < 9; ++k) {
        float2 v;
        v = p0[k * DSP2]; r0.x += v.x; r0.y += v.y;
        v = p1[k * DSP2]; r1.x += v.x; r1.y += v.y;
        v = p2[k * DSP2]; r2.x += v.x; r2.y += v.y;
        v = p3[k * DSP2]; r3.x += v.x; r3.y += v.y;
        v = p4[k * DSP2]; r4.x += v.x; r4.y += v.y;
    }
    float2 l0 = p0[9 * DSP2], l1 = p1[9 * DSP2], l2 = p2[9 * DSP2],
           l3 = p3[9 * DSP2], l4 = p4[9 * DSP2];
    float2 t0 = p0[0], t1 = p1[0], t2 = p2[0], t3 = p3[0], t4 = p4[0];

    const bool v0 = (lane >= 2 && lane <= 29) && (w < WW);
    const bool v1 = (lane >= 2 && lane <= 29) && (w + 1 < WW);
    float facc = 0.f;

    for (int c = 0; c < DC; ++c) {
        r0.x += l0.x - t0.x; r0.y += l0.y - t0.y;
        r1.x += l1.x - t1.x; r1.y += l1.y - t1.y;
        r2.x += l2.x - t2.x; r2.y += l2.y - t2.y;
        r3.x += l3.x - t3.x; r3.y += l3.y - t3.y;
        r4.x += l4.x - t4.x; r4.y += l4.y - t4.y;

        // advance pointers & prefetch next lead/trail (unconditional)
        p0 += DSP2; p1 += DSP2; p2 += DSP2; p3 += DSP2; p4 += DSP2;
        l0 = p0[9 * DSP2]; t0 = p0[0];
        l1 = p1[9 * DSP2]; t1 = p1[0];
        l2 = p2[9 * DSP2]; t2 = p2[0];
        l3 = p3[9 * DSP2]; t3 = p3[0];
        l4 = p4[9 * DSP2]; t4 = p4[0];

        // pair-sum shuffle box: 2 outputs per field
        float b00, b01, b10, b11, b20, b21, b30, b31, b40, b41;
        {
            float P = r0.x + r0.y;
            float Pm2 = __shfl_up_sync(0xffffffffu, P, 2);
            float Pm1 = __shfl_up_sync(0xffffffffu, P, 1);
            float Pp1 = __shfl_down_sync(0xffffffffu, P, 1);
            float Pp2 = __shfl_down_sync(0xffffffffu, P, 2);
            float ap2 = __shfl_down_sync(0xffffffffu, r0.x, 2);
            float bm2 = __shfl_up_sync(0xffffffffu, r0.y, 2);
            float com = Pm1 + P + Pp1;
            b00 = com + Pm2 + ap2;
            b01 = com + Pp2 + bm2;
        }
        {
            float P = r1.x + r1.y;
            float Pm2 = __shfl_up_sync(0xffffffffu, P, 2);
            float Pm1 = __shfl_up_sync(0xffffffffu, P, 1);
            float Pp1 = __shfl_down_sync(0xffffffffu, P, 1);
            float Pp2 = __shfl_down_sync(0xffffffffu, P, 2);
            float ap2 = __shfl_down_sync(0xffffffffu, r1.x, 2);
            float bm2 = __shfl_up_sync(0xffffffffu, r1.y, 2);
            float com = Pm1 + P + Pp1;
            b10 = com + Pm2 + ap2;
            b11 = com + Pp2 + bm2;
        }
        {
            float P = r2.x + r2.y;
            float Pm2 = __shfl_up_sync(0xffffffffu, P, 2);
            float Pm1 = __shfl_up_sync(0xffffffffu, P, 1);
            float Pp1 = __shfl_down_sync(0xffffffffu, P, 1);
            float Pp2 = __shfl_down_sync(0xffffffffu, P, 2);
            float ap2 = __shfl_down_sync(0xffffffffu, r2.x, 2);
            float bm2 = __shfl_up_sync(0xffffffffu, r2.y, 2);
            float com = Pm1 + P + Pp1;
            b20 = com + Pm2 + ap2;
            b21 = com + Pp2 + bm2;
        }
        {
            float P = r3.x + r3.y;
            float Pm2 = __shfl_up_sync(0xffffffffu, P, 2);
            float Pm1 = __shfl_up_sync(0xffffffffu, P, 1);
            float Pp1 = __shfl_down_sync(0xffffffffu, P, 1);
            float Pp2 = __shfl_down_sync(0xffffffffu, P, 2);
            float ap2 = __shfl_down_sync(0xffffffffu, r3.x, 2);
            float bm2 = __shfl_up_sync(0xffffffffu, r3.y, 2);
            float com = Pm1 + P + Pp1;
            b30 = com + Pm2 + ap2;
            b31 = com + Pp2 + bm2;
        }
        {
            float P = r4.x + r4.y;
            float Pm2 = __shfl_up_sync(0xffffffffu, P, 2);
            float Pm1 = __shfl_up_sync(0xffffffffu, P, 1);
            float Pp1 = __shfl_down_sync(0xffffffffu, P, 1);
            float Pp2 = __shfl_down_sync(0xffffffffu, P, 2);
            float ap2 = __shfl_down_sync(0xffffffffu, r4.x, 2);
            float bm2 = __shfl_up_sync(0xffffffffu, r4.y, 2);
            float com = Pm1 + P + Pp1;
            b40 = com + Pm2 + ap2;
            b41 = com + Pp2 + bm2;
        }

        if (v0) facc += cc_val(b00, b10, b20, b30, b40);
        if (v1) facc += cc_val(b01, b11, b21, b31, b41);
    }

    // block reduction (promote to double)
    double acc = (double)facc;
#pragma unroll
    for (int off = 16; off; off >>= 1) acc += __shfl_down_sync(0xffffffffu, acc, off);
    __shared__ double sred[WPB];
    int ln = threadIdx.x & 31;
    int wd = threadIdx.x >> 5;
    if (ln == 0) sred[wd] = acc;
    __syncthreads();
    if (wd == 0) {
        double a = (ln < WPB) ? sred[ln] : 0.0;
#pragma unroll
        for (int off = 2; off; off >>= 1) a += __shfl_down_sync(0xffffffffu, a, off);
        if (ln == 0) {
            atomicAdd(&g_acc, a);
            __threadfence();
            unsigned int old = atomicAdd(&g_done, 1u);
            if (old == (unsigned int)NBLK2 - 1u) {
                out[0] = (float)(-g_acc / (double)NVOX);
                g_acc = 0.0;
                g_done = 0u;
            }
        }
    }
}

extern "C" void kernel_launch(void* const* d_in, const int* in_sizes, int n_in,
                              void* d_out, int out_size) {
    const float* in = (const float*)d_in[0];
    const float* tg = (const float*)d_in[1];
    float* out = (float*)d_out;

    k_pass1<<<NTH1 / 256, 256>>>(in, tg);      // 600 blocks
    k_pass23<<<NBLK2, NT2>>>(out);             // 1152 blocks x 128
}